// round 9
// baseline (speedup 1.0000x reference)
#include <cuda_runtime.h>

// Bilinear_3882650435896: conv_transpose2d(x, w, stride=2) with block-diagonal
// w (per-channel bilinear filter) == depthwise 2x upsample.
// x: (4,256,128,128) f32 -> out: (4,256,258,258) f32.
//
// R8 -> R9: lane covers 4 consecutive output cols (4m..4m+3, m=lane+32k).
// Loads per row: 1 scalar LDS (col 2m-1) + 1 aligned LDS.64 (cols 2m,2m+1)
// -> 8 LDS per pair (was 16). Stores: row 2r via STG.128 (16B-aligned:
// pair stride 2064=129*16), row 2r+1 via 2x STG.64 (8-mod-16, forced).
// Warp store requests stay contiguous (512B). Separable filter from R8.

#define C     256
#define HIN   128
#define HOUT  258
#define NROWS 17         // input rows staged per block (R-1 .. R+15)
#define SROW  136        // smem row stride in words (4 left-pad + 128 + 4)
#define PAIRS 16         // row pairs per block

__global__ void __launch_bounds__(256)
bilinear_up_kernel(const float* __restrict__ x,
                   const float* __restrict__ w,
                   float* __restrict__ out)
{
    const int nc = blockIdx.y;            // n*C + c
    const int c  = nc & (C - 1);
    const int R  = blockIdx.x * PAIRS;    // first row-pair index of this block

    __shared__ __align__(16) float tile[NROWS * SROW];   // 9.25 KB

    if (threadIdx.x < NROWS * 4) {        // zero 4-word left pad per row
        const int row = threadIdx.x >> 2;
        tile[row * SROW + (threadIdx.x & 3)] = 0.f;
    }

    // Stage 17 input rows as float4: 544 vectors across 256 threads.
    const float4* __restrict__ x4 =
        reinterpret_cast<const float4*>(x + (size_t)nc * (HIN * HIN));
    const float4 z4 = make_float4(0.f, 0.f, 0.f, 0.f);
#pragma unroll
    for (int i = threadIdx.x; i < NROWS * 32; i += 256) {
        const int row = i >> 5;
        const int j   = i & 31;
        const int g   = R - 1 + row;
        const float4 v = (g >= 0 && g < HIN) ? __ldg(&x4[g * 32 + j]) : z4;
        *reinterpret_cast<float4*>(&tile[row * SROW + 4 + 4 * j]) = v;
    }

    // Separable filter: f[kh][kw] = g[kh]*g[kw] (exact for bilinear taps).
    const float* __restrict__ wc = w + (size_t)c * (C + 1) * 16;
    const float g1 = sqrtf(__ldg(wc + 5));     // f[1][1]
    const float g0 = __ldg(wc + 1)  / g1;      // f[0][1]
    const float g2 = __ldg(wc + 9)  / g1;      // f[2][1]
    const float g3 = __ldg(wc + 13) / g1;      // f[3][1]

    __syncthreads();

    const int warp = threadIdx.x >> 5;
    const int lane = threadIdx.x & 31;

#pragma unroll
    for (int p = 0; p < 2; p++) {
        const int tr = warp + 8 * p;      // tile row of input row r-1
        const int r  = R + tr;            // row-pair index, valid if <= 128
        if (r > HIN) continue;

        const float* __restrict__ sm0 = &tile[tr * SROW];        // row r-1
        const float* __restrict__ sm1 = &tile[(tr + 1) * SROW];  // row r

        float* __restrict__ o0 =
            out + (size_t)nc * (HOUT * HOUT) + (size_t)(2 * r) * HOUT;
        float* __restrict__ o1 = o0 + HOUT;

        float x127_0 = 0.f, x127_1 = 0.f;     // lane31 keeps input col 127

#pragma unroll
        for (int k = 0; k < 2; k++) {
            const int m = lane + 32 * k;      // 0..63: out cols 4m..4m+3
            // Input cols 2m-1 (scalar, pad covers m=0) and 2m,2m+1 (LDS.64).
            const float  a0 = sm0[2 * m + 3];
            const float2 b0 = *reinterpret_cast<const float2*>(sm0 + 2 * m + 4);
            const float  a1 = sm1[2 * m + 3];
            const float2 b1 = *reinterpret_cast<const float2*>(sm1 + 2 * m + 4);
            if (k == 1 && lane == 31) { x127_0 = b0.y; x127_1 = b1.y; }

            // Column stage per input row: out col 4m   <- g0*x[2m]  +g2*x[2m-1]
            //                             out col 4m+1 <- g1*x[2m]  +g3*x[2m-1]
            //                             out col 4m+2 <- g0*x[2m+1]+g2*x[2m]
            //                             out col 4m+3 <- g1*x[2m+1]+g3*x[2m]
            const float cA0 = g0 * b0.x + g2 * a0;
            const float cB0 = g1 * b0.x + g3 * a0;
            const float cC0 = g0 * b0.y + g2 * b0.x;
            const float cD0 = g1 * b0.y + g3 * b0.x;
            const float cA1 = g0 * b1.x + g2 * a1;
            const float cB1 = g1 * b1.x + g3 * a1;
            const float cC1 = g0 * b1.y + g2 * b1.x;
            const float cD1 = g1 * b1.y + g3 * b1.x;

            // Row stage: row 2r <- g0*rowr + g2*row(r-1); row 2r+1 <- g1/g3.
            const float4 v0 = make_float4(g0 * cA1 + g2 * cA0,
                                          g0 * cB1 + g2 * cB0,
                                          g0 * cC1 + g2 * cC0,
                                          g0 * cD1 + g2 * cD0);
            const float2 u0 = make_float2(g1 * cA1 + g3 * cA0,
                                          g1 * cB1 + g3 * cB0);
            const float2 u1 = make_float2(g1 * cC1 + g3 * cC0,
                                          g1 * cD1 + g3 * cD0);

            __stcs(reinterpret_cast<float4*>(o0 + 4 * m), v0);
            __stcs(reinterpret_cast<float2*>(o1 + 4 * m), u0);
            __stcs(reinterpret_cast<float2*>(o1 + 4 * m + 2), u1);
        }

        // Tail (out cols 256,257): only input col 127 contributes (kw=2,3).
        if (lane == 31) {
            const float p1e = g2 * x127_1, p1o = g3 * x127_1;   // row r
            const float p0e = g2 * x127_0, p0o = g3 * x127_0;   // row r-1
            __stcs(reinterpret_cast<float2*>(o0 + 256),
                   make_float2(g0 * p1e + g2 * p0e, g0 * p1o + g2 * p0o));
            __stcs(reinterpret_cast<float2*>(o1 + 256),
                   make_float2(g1 * p1e + g3 * p0e, g1 * p1o + g3 * p0o));
        }
    }
}

extern "C" void kernel_launch(void* const* d_in, const int* in_sizes, int n_in,
                              void* d_out, int out_size)
{
    const float* x = (const float*)d_in[0];   // (4,256,128,128)
    const float* w = (const float*)d_in[1];   // (256,256,4,4)
    float* out = (float*)d_out;               // (4,256,258,258)

    dim3 block(256);
    dim3 grid((HIN + 1 + PAIRS - 1) / PAIRS, 4 * C);   // (9, 1024)
    bilinear_up_kernel<<<grid, block>>>(x, w, out);
}

// round 10
// speedup vs baseline: 1.0610x; 1.0610x over previous
#include <cuda_runtime.h>

// Bilinear_3882650435896: conv_transpose2d(x, w, stride=2) with block-diagonal
// w (per-channel bilinear filter) == depthwise 2x upsample.
// x: (4,256,128,128) f32 -> out: (4,256,258,258) f32.
//
// R8 -> R10: dense STG.128 for BOTH output rows. Lane m=lane+32k covers
// row 2r cols 4m..4m+3 (addr o0+16m, 16B-aligned) and row 2r+1 cols
// 4m+2..4m+5 (addr o1+16m+8; o1 = +1032B = 8 mod 16, so 16B-aligned too).
// Store width == lane stride (16B) -> fully dense warp requests (R9's gap
// bug fixed). Loads/row: x[2m-1] scalar, x[2m..2m+1] LDS.64, x[2m+2]
// scalar; zeroed right pad makes x[128]=0 so lane31's cE/cF cover the
// odd-row tail for free. Separable filter (R8).

#define C     256
#define HIN   128
#define HOUT  258
#define NROWS 17         // input rows staged per block (R-1 .. R+15)
#define SROW  136        // smem row: 4 left-pad + 128 data + 4 right-pad
#define PAIRS 16         // row pairs per block

__global__ void __launch_bounds__(256)
bilinear_up_kernel(const float* __restrict__ x,
                   const float* __restrict__ w,
                   float* __restrict__ out)
{
    const int nc = blockIdx.y;            // n*C + c
    const int c  = nc & (C - 1);
    const int R  = blockIdx.x * PAIRS;    // first row-pair index of this block

    __shared__ __align__(16) float tile[NROWS * SROW];   // 9.25 KB

    // Zero both pads (8 words per row): x[-1] -> tile[.][3], x[128] -> [132].
    if (threadIdx.x < NROWS * 8) {
        const int row = threadIdx.x >> 3;
        const int wi  = threadIdx.x & 7;
        tile[row * SROW + (wi < 4 ? wi : 128 + wi)] = 0.f;
    }

    // Stage 17 input rows as float4: 544 vectors across 256 threads.
    const float4* __restrict__ x4 =
        reinterpret_cast<const float4*>(x + (size_t)nc * (HIN * HIN));
    const float4 z4 = make_float4(0.f, 0.f, 0.f, 0.f);
#pragma unroll
    for (int i = threadIdx.x; i < NROWS * 32; i += 256) {
        const int row = i >> 5;
        const int j   = i & 31;
        const int g   = R - 1 + row;
        const float4 v = (g >= 0 && g < HIN) ? __ldg(&x4[g * 32 + j]) : z4;
        *reinterpret_cast<float4*>(&tile[row * SROW + 4 + 4 * j]) = v;
    }

    // Separable filter: f[kh][kw] = g[kh]*g[kw] (exact for bilinear taps).
    const float* __restrict__ wc = w + (size_t)c * (C + 1) * 16;
    const float g1 = sqrtf(__ldg(wc + 5));     // f[1][1]
    const float g0 = __ldg(wc + 1)  / g1;      // f[0][1]
    const float g2 = __ldg(wc + 9)  / g1;      // f[2][1]
    const float g3 = __ldg(wc + 13) / g1;      // f[3][1]

    __syncthreads();

    const int warp = threadIdx.x >> 5;
    const int lane = threadIdx.x & 31;

#pragma unroll
    for (int p = 0; p < 2; p++) {
        const int tr = warp + 8 * p;      // tile row of input row r-1
        const int r  = R + tr;            // row-pair index, valid if <= 128
        if (r > HIN) continue;

        const float* __restrict__ sm0 = &tile[tr * SROW];        // row r-1
        const float* __restrict__ sm1 = &tile[(tr + 1) * SROW];  // row r

        float* __restrict__ o0 =
            out + (size_t)nc * (HOUT * HOUT) + (size_t)(2 * r) * HOUT;
        float* __restrict__ o1 = o0 + HOUT;

#pragma unroll
        for (int k = 0; k < 2; k++) {
            const int m = lane + 32 * k;  // 0..63
            // x[2m-1], x[2m..2m+1], x[2m+2] per row (pads give 0 at edges).
            const float  a0 = sm0[2 * m + 3];
            const float2 b0 = *reinterpret_cast<const float2*>(sm0 + 2 * m + 4);
            const float  e0 = sm0[2 * m + 6];
            const float  a1 = sm1[2 * m + 3];
            const float2 b1 = *reinterpret_cast<const float2*>(sm1 + 2 * m + 4);
            const float  e1 = sm1[2 * m + 6];

            // Column combos per row: out col 2t (even) <- g0*x[t]+g2*x[t-1],
            //                        out col 2t+1(odd) <- g1*x[t]+g3*x[t-1].
            const float cA0 = g0 * b0.x + g2 * a0;    // col 4m
            const float cB0 = g1 * b0.x + g3 * a0;    // col 4m+1
            const float cC0 = g0 * b0.y + g2 * b0.x;  // col 4m+2
            const float cD0 = g1 * b0.y + g3 * b0.x;  // col 4m+3
            const float cE0 = g0 * e0   + g2 * b0.y;  // col 4m+4
            const float cF0 = g1 * e0   + g3 * b0.y;  // col 4m+5
            const float cA1 = g0 * b1.x + g2 * a1;
            const float cB1 = g1 * b1.x + g3 * a1;
            const float cC1 = g0 * b1.y + g2 * b1.x;
            const float cD1 = g1 * b1.y + g3 * b1.x;
            const float cE1 = g0 * e1   + g2 * b1.y;
            const float cF1 = g1 * e1   + g3 * b1.y;

            // Row 2r: cols 4m..4m+3 (dense STG.128, 16B-aligned).
            __stcs(reinterpret_cast<float4*>(o0 + 4 * m),
                   make_float4(g0 * cA1 + g2 * cA0, g0 * cB1 + g2 * cB0,
                               g0 * cC1 + g2 * cC0, g0 * cD1 + g2 * cD0));
            // Row 2r+1: cols 4m+2..4m+5 (dense STG.128; +8B cancels o1's
            // 8-mod-16 offset). m=63 writes cols 254..257 incl. tail (x[128]=0).
            __stcs(reinterpret_cast<float4*>(o1 + 4 * m + 2),
                   make_float4(g1 * cC1 + g3 * cC0, g1 * cD1 + g3 * cD0,
                               g1 * cE1 + g3 * cE0, g1 * cF1 + g3 * cF0));

            // Row 2r+1 cols 0,1 (lane0, k=0): reuse cA/cB (x[-1]=0).
            if (k == 0 && lane == 0)
                __stcs(reinterpret_cast<float2*>(o1),
                       make_float2(g1 * cA1 + g3 * cA0, g1 * cB1 + g3 * cB0));
            // Row 2r cols 256,257 (lane31, k=1): reuse cE/cF (x[128]=0).
            if (k == 1 && lane == 31)
                __stcs(reinterpret_cast<float2*>(o0 + 256),
                       make_float2(g0 * cE1 + g2 * cE0, g0 * cF1 + g2 * cF0));
        }
    }
}

extern "C" void kernel_launch(void* const* d_in, const int* in_sizes, int n_in,
                              void* d_out, int out_size)
{
    const float* x = (const float*)d_in[0];   // (4,256,128,128)
    const float* w = (const float*)d_in[1];   // (256,256,4,4)
    float* out = (float*)d_out;               // (4,256,258,258)

    dim3 block(256);
    dim3 grid((HIN + 1 + PAIRS - 1) / PAIRS, 4 * C);   // (9, 1024)
    bilinear_up_kernel<<<grid, block>>>(x, w, out);
}

// round 11
// speedup vs baseline: 1.0640x; 1.0029x over previous
#include <cuda_runtime.h>

// Bilinear_3882650435896: conv_transpose2d(x, w, stride=2) with block-diagonal
// w (per-channel bilinear filter) == depthwise 2x upsample.
// x: (4,256,128,128) f32 -> out: (4,256,258,258) f32.
//
// R10 -> R11: grid.x 9 -> 8. The old 9th block column did full staging for a
// single valid row pair (11% of CTAs nearly idle). Now NROWS=18 (R-1..R+16,
// OOB rows zero-filled), blocks run their 16 pairs unguarded, and the last
// block (R==112) folds in the final pair r=128 on warp 0 using tile rows
// 16/17 (row 128 == zeros). Inner body identical to R10: dense STG.128 on
// both output rows (lane stride == store width), separable filter.

#define C     256
#define HIN   128
#define HOUT  258
#define NROWS 18         // input rows staged per block (R-1 .. R+16)
#define SROW  136        // smem row: 4 left-pad + 128 data + 4 right-pad
#define PAIRS 16         // row pairs per block (plus 1 folded tail pair)

__device__ __forceinline__ void do_pair(
    const float* __restrict__ sm0, const float* __restrict__ sm1,
    float* __restrict__ o0, float* __restrict__ o1, int lane,
    float g0, float g1, float g2, float g3)
{
#pragma unroll
    for (int k = 0; k < 2; k++) {
        const int m = lane + 32 * k;  // 0..63
        // x[2m-1], x[2m..2m+1], x[2m+2] per row (pads give 0 at edges).
        const float  a0 = sm0[2 * m + 3];
        const float2 b0 = *reinterpret_cast<const float2*>(sm0 + 2 * m + 4);
        const float  e0 = sm0[2 * m + 6];
        const float  a1 = sm1[2 * m + 3];
        const float2 b1 = *reinterpret_cast<const float2*>(sm1 + 2 * m + 4);
        const float  e1 = sm1[2 * m + 6];

        // Column combos: out col 2t <- g0*x[t]+g2*x[t-1]; 2t+1 <- g1/g3.
        const float cA0 = g0 * b0.x + g2 * a0;    // col 4m
        const float cB0 = g1 * b0.x + g3 * a0;    // col 4m+1
        const float cC0 = g0 * b0.y + g2 * b0.x;  // col 4m+2
        const float cD0 = g1 * b0.y + g3 * b0.x;  // col 4m+3
        const float cE0 = g0 * e0   + g2 * b0.y;  // col 4m+4
        const float cF0 = g1 * e0   + g3 * b0.y;  // col 4m+5
        const float cA1 = g0 * b1.x + g2 * a1;
        const float cB1 = g1 * b1.x + g3 * a1;
        const float cC1 = g0 * b1.y + g2 * b1.x;
        const float cD1 = g1 * b1.y + g3 * b1.x;
        const float cE1 = g0 * e1   + g2 * b1.y;
        const float cF1 = g1 * e1   + g3 * b1.y;

        // Row 2r: cols 4m..4m+3 (dense STG.128, 16B-aligned).
        __stcs(reinterpret_cast<float4*>(o0 + 4 * m),
               make_float4(g0 * cA1 + g2 * cA0, g0 * cB1 + g2 * cB0,
                           g0 * cC1 + g2 * cC0, g0 * cD1 + g2 * cD0));
        // Row 2r+1: cols 4m+2..4m+5 (dense STG.128; +8B cancels o1's
        // 8-mod-16 offset). m=63 covers cols 254..257 incl. tail (x[128]=0).
        __stcs(reinterpret_cast<float4*>(o1 + 4 * m + 2),
               make_float4(g1 * cC1 + g3 * cC0, g1 * cD1 + g3 * cD0,
                           g1 * cE1 + g3 * cE0, g1 * cF1 + g3 * cF0));

        // Row 2r+1 cols 0,1 (lane0, k=0): reuse cA/cB (x[-1]=0).
        if (k == 0 && lane == 0)
            __stcs(reinterpret_cast<float2*>(o1),
                   make_float2(g1 * cA1 + g3 * cA0, g1 * cB1 + g3 * cB0));
        // Row 2r cols 256,257 (lane31, k=1): reuse cE/cF (x[128]=0).
        if (k == 1 && lane == 31)
            __stcs(reinterpret_cast<float2*>(o0 + 256),
                   make_float2(g0 * cE1 + g2 * cE0, g0 * cF1 + g2 * cF0));
    }
}

__global__ void __launch_bounds__(256)
bilinear_up_kernel(const float* __restrict__ x,
                   const float* __restrict__ w,
                   float* __restrict__ out)
{
    const int nc = blockIdx.y;            // n*C + c
    const int c  = nc & (C - 1);
    const int R  = blockIdx.x * PAIRS;    // first row-pair index, 0..112

    __shared__ __align__(16) float tile[NROWS * SROW];   // 9.56 KB

    // Zero both pads (8 words per row): x[-1] -> tile[.][3], x[128] -> [132].
    if (threadIdx.x < NROWS * 8) {
        const int row = threadIdx.x >> 3;
        const int wi  = threadIdx.x & 7;
        tile[row * SROW + (wi < 4 ? wi : 128 + wi)] = 0.f;
    }

    // Stage 18 input rows as float4: 576 vectors across 256 threads
    // (rows >= HIN zero-fill; covers the r=128 tail pair's "row 128").
    const float4* __restrict__ x4 =
        reinterpret_cast<const float4*>(x + (size_t)nc * (HIN * HIN));
    const float4 z4 = make_float4(0.f, 0.f, 0.f, 0.f);
#pragma unroll
    for (int i = threadIdx.x; i < NROWS * 32; i += 256) {
        const int row = i >> 5;
        const int j   = i & 31;
        const int g   = R - 1 + row;
        const float4 v = (g >= 0 && g < HIN) ? __ldg(&x4[g * 32 + j]) : z4;
        *reinterpret_cast<float4*>(&tile[row * SROW + 4 + 4 * j]) = v;
    }

    // Separable filter: f[kh][kw] = g[kh]*g[kw] (exact for bilinear taps).
    const float* __restrict__ wc = w + (size_t)c * (C + 1) * 16;
    const float g1 = sqrtf(__ldg(wc + 5));     // f[1][1]
    const float g0 = __ldg(wc + 1)  / g1;      // f[0][1]
    const float g2 = __ldg(wc + 9)  / g1;      // f[2][1]
    const float g3 = __ldg(wc + 13) / g1;      // f[3][1]

    __syncthreads();

    const int warp = threadIdx.x >> 5;
    const int lane = threadIdx.x & 31;
    float* __restrict__ oplane = out + (size_t)nc * (HOUT * HOUT);

#pragma unroll
    for (int p = 0; p < 2; p++) {
        const int tr = warp + 8 * p;      // tile row of input row r-1
        const int r  = R + tr;            // row-pair index, always <= 127
        float* __restrict__ o0 = oplane + (size_t)(2 * r) * HOUT;
        do_pair(&tile[tr * SROW], &tile[(tr + 1) * SROW],
                o0, o0 + HOUT, lane, g0, g1, g2, g3);
    }

    // Folded tail pair r = 128 (output rows 256,257): last block only,
    // warp 0, tile rows 16 (input row 127) and 17 (zeros == "row 128").
    if (R == HIN - PAIRS && warp == 0) {
        float* __restrict__ o0 = oplane + (size_t)(2 * HIN) * HOUT;
        do_pair(&tile[16 * SROW], &tile[17 * SROW],
                o0, o0 + HOUT, lane, g0, g1, g2, g3);
    }
}

extern "C" void kernel_launch(void* const* d_in, const int* in_sizes, int n_in,
                              void* d_out, int out_size)
{
    const float* x = (const float*)d_in[0];   // (4,256,128,128)
    const float* w = (const float*)d_in[1];   // (256,256,4,4)
    float* out = (float*)d_out;               // (4,256,258,258)

    dim3 block(256);
    dim3 grid(HIN / PAIRS, 4 * C);            // (8, 1024)
    bilinear_up_kernel<<<grid, block>>>(x, w, out);
}

// round 12
// speedup vs baseline: 1.0665x; 1.0023x over previous
#include <cuda_runtime.h>
#include <cstdint>

// Bilinear_3882650435896: conv_transpose2d(x, w, stride=2) with block-diagonal
// w (per-channel bilinear filter) == depthwise 2x upsample.
// x: (4,256,128,128) f32 -> out: (4,256,258,258) f32.
//
// R11 -> R12: CTA-granularity async bulk store. A block's 16 row pairs form
// ONE contiguous 33,024B gmem span (16B-aligned). Compute all pairs into a
// 33KB smem buffer (R10's dense STS.128 body), then a single
// cp.async.bulk.global.shared::cta per CTA with one wait at the end.
// SM retires zero global-store wavefronts; the async engine writes full
// lines. (R6 failed with 2KB per-warp copies + per-warp blocking waits —
// this fixes both.) Tail pair r=128 keeps direct stores.

#define C     256
#define HIN   128
#define HOUT  258
#define NROWS 18         // input rows staged per block (R-1 .. R+16)
#define SROW  136        // smem row: 4 left-pad + 128 data + 4 right-pad
#define PAIRS 16         // row pairs per block
#define OPAIR (2 * HOUT) // 516 floats per pair
#define OBYTES (PAIRS * OPAIR * 4)   // 33024 B per CTA

__device__ __forceinline__ uint32_t smem_u32(const void* p) {
    uint32_t a;
    asm("{ .reg .u64 t; cvta.to.shared.u64 t, %1; cvt.u32.u64 %0, t; }"
        : "=r"(a) : "l"(p));
    return a;
}

// Computes one output row pair from input rows sm0 (r-1) and sm1 (r) into
// b0 (row 2r) / b1 (row 2r+1). Generic pointers: smem (main) or gmem (tail).
__device__ __forceinline__ void do_pair(
    const float* __restrict__ sm0, const float* __restrict__ sm1,
    float* __restrict__ b0, float* __restrict__ b1, int lane,
    float g0, float g1, float g2, float g3)
{
#pragma unroll
    for (int k = 0; k < 2; k++) {
        const int m = lane + 32 * k;  // 0..63
        const float  a0 = sm0[2 * m + 3];
        const float2 v0 = *reinterpret_cast<const float2*>(sm0 + 2 * m + 4);
        const float  e0 = sm0[2 * m + 6];
        const float  a1 = sm1[2 * m + 3];
        const float2 v1 = *reinterpret_cast<const float2*>(sm1 + 2 * m + 4);
        const float  e1 = sm1[2 * m + 6];

        const float cA0 = g0 * v0.x + g2 * a0;    // col 4m
        const float cB0 = g1 * v0.x + g3 * a0;    // col 4m+1
        const float cC0 = g0 * v0.y + g2 * v0.x;  // col 4m+2
        const float cD0 = g1 * v0.y + g3 * v0.x;  // col 4m+3
        const float cE0 = g0 * e0   + g2 * v0.y;  // col 4m+4
        const float cF0 = g1 * e0   + g3 * v0.y;  // col 4m+5
        const float cA1 = g0 * v1.x + g2 * a1;
        const float cB1 = g1 * v1.x + g3 * a1;
        const float cC1 = g0 * v1.y + g2 * v1.x;
        const float cD1 = g1 * v1.y + g3 * v1.x;
        const float cE1 = g0 * e1   + g2 * v1.y;
        const float cF1 = g1 * e1   + g3 * v1.y;

        // Row 2r: cols 4m..4m+3 (dense 16B stores, 16B-aligned).
        *reinterpret_cast<float4*>(b0 + 4 * m) =
            make_float4(g0 * cA1 + g2 * cA0, g0 * cB1 + g2 * cB0,
                        g0 * cC1 + g2 * cC0, g0 * cD1 + g2 * cD0);
        // Row 2r+1: cols 4m+2..4m+5 (+8B cancels the 8-mod-16 row offset).
        *reinterpret_cast<float4*>(b1 + 4 * m + 2) =
            make_float4(g1 * cC1 + g3 * cC0, g1 * cD1 + g3 * cD0,
                        g1 * cE1 + g3 * cE0, g1 * cF1 + g3 * cF0);

        if (k == 0 && lane == 0)      // row 2r+1 cols 0,1 (x[-1]=0)
            *reinterpret_cast<float2*>(b1) =
                make_float2(g1 * cA1 + g3 * cA0, g1 * cB1 + g3 * cB0);
        if (k == 1 && lane == 31)     // row 2r cols 256,257 (x[128]=0)
            *reinterpret_cast<float2*>(b0 + 256) =
                make_float2(g0 * cE1 + g2 * cE0, g0 * cF1 + g2 * cF0);
    }
}

__global__ void __launch_bounds__(256)
bilinear_up_kernel(const float* __restrict__ x,
                   const float* __restrict__ w,
                   float* __restrict__ out)
{
    const int nc = blockIdx.y;            // n*C + c
    const int c  = nc & (C - 1);
    const int R  = blockIdx.x * PAIRS;    // first row-pair index, 0..112

    __shared__ __align__(16) float tile[NROWS * SROW];     // 9.79 KB
    __shared__ __align__(16) float obuf[PAIRS * OPAIR];    // 33.0 KB

    // Zero both pads (8 words per row).
    if (threadIdx.x < NROWS * 8) {
        const int row = threadIdx.x >> 3;
        const int wi  = threadIdx.x & 7;
        tile[row * SROW + (wi < 4 ? wi : 128 + wi)] = 0.f;
    }

    // Stage 18 input rows as float4 (OOB rows zero-filled).
    const float4* __restrict__ x4 =
        reinterpret_cast<const float4*>(x + (size_t)nc * (HIN * HIN));
    const float4 z4 = make_float4(0.f, 0.f, 0.f, 0.f);
#pragma unroll
    for (int i = threadIdx.x; i < NROWS * 32; i += 256) {
        const int row = i >> 5;
        const int j   = i & 31;
        const int g   = R - 1 + row;
        const float4 v = (g >= 0 && g < HIN) ? __ldg(&x4[g * 32 + j]) : z4;
        *reinterpret_cast<float4*>(&tile[row * SROW + 4 + 4 * j]) = v;
    }

    // Separable filter: f[kh][kw] = g[kh]*g[kw] (exact for bilinear taps).
    const float* __restrict__ wc = w + (size_t)c * (C + 1) * 16;
    const float g1 = sqrtf(__ldg(wc + 5));
    const float g0 = __ldg(wc + 1)  / g1;
    const float g2 = __ldg(wc + 9)  / g1;
    const float g3 = __ldg(wc + 13) / g1;

    __syncthreads();

    const int warp = threadIdx.x >> 5;
    const int lane = threadIdx.x & 31;

#pragma unroll
    for (int p = 0; p < 2; p++) {
        const int tr = warp + 8 * p;      // pair index within block, 0..15
        float* __restrict__ b0 = &obuf[tr * OPAIR];
        do_pair(&tile[tr * SROW], &tile[(tr + 1) * SROW],
                b0, b0 + HOUT, lane, g0, g1, g2, g3);
    }

    // Tail pair r=128 (output rows 256,257): last block column, warp 0,
    // direct global stores (tile row 17 is zeros == "input row 128").
    if (R == HIN - PAIRS && warp == 0) {
        float* __restrict__ t0 =
            out + (size_t)nc * (HOUT * HOUT) + (size_t)(2 * HIN) * HOUT;
        do_pair(&tile[16 * SROW], &tile[17 * SROW],
                t0, t0 + HOUT, lane, g0, g1, g2, g3);
    }

    __syncthreads();

    // One bulk store of the CTA's whole 33,024B contiguous output span.
    if (threadIdx.x == 0) {
        asm volatile("fence.proxy.async.shared::cta;" ::: "memory");
        float* gdst = out + (size_t)nc * (HOUT * HOUT) + (size_t)R * OPAIR;
        const uint32_t saddr = smem_u32(obuf);
        asm volatile(
            "cp.async.bulk.global.shared::cta.bulk_group [%0], [%1], %2;"
            :: "l"(gdst), "r"(saddr), "n"(OBYTES) : "memory");
        asm volatile("cp.async.bulk.commit_group;" ::: "memory");
        asm volatile("cp.async.bulk.wait_group 0;" ::: "memory");
    }
}

extern "C" void kernel_launch(void* const* d_in, const int* in_sizes, int n_in,
                              void* d_out, int out_size)
{
    const float* x = (const float*)d_in[0];   // (4,256,128,128)
    const float* w = (const float*)d_in[1];   // (256,256,4,4)
    float* out = (float*)d_out;               // (4,256,258,258)

    dim3 block(256);
    dim3 grid(HIN / PAIRS, 4 * C);            // (8, 1024)
    bilinear_up_kernel<<<grid, block>>>(x, w, out);
}